// round 5
// baseline (speedup 1.0000x reference)
#include <cuda_runtime.h>
#include <cuda_bf16.h>
#include <cstdint>

#define NBATCH 4096
#define NTOK   64
#define NDIM   256
#define NHEADS 8
#define HD     32
#define NROWS  (NBATCH * NTOK)   // 262144

// ---------------- device scratch ---------------------------------------------
__device__ float g_q[NBATCH * NHEADS * NTOK * HD];
__device__ float g_k[NBATCH * NHEADS * NTOK * HD];
__device__ float g_v[NBATCH * NHEADS * NTOK * HD];
__device__ float g_o[NBATCH * NTOK * NDIM];
__device__ __align__(16) __nv_bfloat16 g_wqh[768 * 256];  // [col][k] hi
__device__ __align__(16) __nv_bfloat16 g_wql[768 * 256];  // [col][k] lo
__device__ __align__(16) __nv_bfloat16 g_wph[256 * 256];
__device__ __align__(16) __nv_bfloat16 g_wpl[256 * 256];
__device__ float g_bias[NHEADS * NTOK * NTOK];            // [h][n][m]

// ---------------- helpers ----------------------------------------------------
__device__ __forceinline__ uint32_t s2u(const void* p) {
    return (uint32_t)__cvta_generic_to_shared(p);
}
__device__ __forceinline__ void split1(float a, __nv_bfloat16& h, __nv_bfloat16& l) {
    h = __float2bfloat16(a);
    l = __float2bfloat16(a - __bfloat162float(h));
}
__device__ __forceinline__ void split2(float a, float b, uint32_t& hi, uint32_t& lo) {
    __nv_bfloat16 ha, la, hb, lb;
    split1(a, ha, la); split1(b, hb, lb);
    __nv_bfloat162 H = __halves2bfloat162(ha, hb);
    __nv_bfloat162 L = __halves2bfloat162(la, lb);
    hi = *(uint32_t*)&H; lo = *(uint32_t*)&L;
}
#define LDM4(r0, r1, r2, r3, addr)                                              \
    asm volatile("ldmatrix.sync.aligned.m8n8.x4.shared.b16 {%0,%1,%2,%3}, [%4];"\
                 : "=r"(r0), "=r"(r1), "=r"(r2), "=r"(r3) : "r"(addr))

__device__ __forceinline__ void mma16(float* c, const uint32_t* a, const uint32_t* b) {
    asm volatile(
        "mma.sync.aligned.m16n8k16.row.col.f32.bf16.bf16.f32 "
        "{%0,%1,%2,%3}, {%4,%5,%6,%7}, {%8,%9}, {%0,%1,%2,%3};"
        : "+f"(c[0]), "+f"(c[1]), "+f"(c[2]), "+f"(c[3])
        : "r"(a[0]), "r"(a[1]), "r"(a[2]), "r"(a[3]), "r"(b[0]), "r"(b[1]));
}

// ---------------------------------------------------------------------------
// Prep: weights -> [col][k] bf16 hi/lo; bias matrix.
// ---------------------------------------------------------------------------
__global__ void prep_w(const float* __restrict__ wq, const float* __restrict__ wkv,
                       const float* __restrict__ pw)
{
    int idx = blockIdx.x * 256 + threadIdx.x;
    if (idx < 768 * 256) {
        int c = idx >> 8, k = idx & 255;
        float v = (c < 256) ? wq[k * 256 + c] : wkv[k * 512 + (c - 256)];
        __nv_bfloat16 h, l; split1(v, h, l);
        g_wqh[idx] = h; g_wql[idx] = l;
    }
    int idx2 = idx - 768 * 256;
    if (idx2 >= 0 && idx2 < 256 * 256) {
        int c = idx2 >> 8, k = idx2 & 255;
        __nv_bfloat16 h, l; split1(pw[k * 256 + c], h, l);
        g_wph[idx2] = h; g_wpl[idx2] = l;
    }
}

__global__ void prep_bias(const float* __restrict__ bias_table,
                          const int* __restrict__ rel_idx)
{
    int idx = blockIdx.x * 256 + threadIdx.x;
    int h = idx >> 12, rm = idx & 4095;
    g_bias[idx] = bias_table[rel_idx[rm] * NHEADS + h];
}

// ---------------------------------------------------------------------------
// bf16 hi/lo GEMM: C[128x128] = A[128x256] @ W^T (+bias). 256 thr / 8 warps
// (2m x 4n), warp tile 64x32. BK=32, double buffered, ldmatrix fragments.
// smem bytes: Ah 0, Al 20480, Bh 40960, Bl 61440  (each [2][128][40] bf16)
// ---------------------------------------------------------------------------
#define AHp(buf, r, c) (smem8 +         ((((buf) * 128 + (r)) * 40 + (c)) * 2))
#define ALp(buf, r, c) (smem8 + 20480 + ((((buf) * 128 + (r)) * 40 + (c)) * 2))
#define BHp(buf, r, c) (smem8 + 40960 + ((((buf) * 128 + (r)) * 40 + (c)) * 2))
#define BLp(buf, r, c) (smem8 + 61440 + ((((buf) * 128 + (r)) * 40 + (c)) * 2))
#define MM_SMEM 81920

__global__ __launch_bounds__(256) void mm_bf16(
    const float* __restrict__ A,
    const __nv_bfloat16* __restrict__ Wh, const __nv_bfloat16* __restrict__ Wl,
    const float* __restrict__ bq, const float* __restrict__ bkv,
    const float* __restrict__ pb, float* __restrict__ outp, int mode)
{
    extern __shared__ __align__(16) char smem8[];
    const int t = threadIdx.x;
    const int lane = t & 31, wid = t >> 5;
    const int wm = wid & 1, wn = wid >> 1;     // 2 x 4 warp grid
    const int gid = lane >> 2, t4 = lane & 3;
    const size_t row0 = (size_t)blockIdx.y * 128;
    const int col0 = blockIdx.x * 128;

    float c[4][4][4];
#pragma unroll
    for (int mt = 0; mt < 4; mt++)
#pragma unroll
        for (int nt = 0; nt < 4; nt++)
#pragma unroll
            for (int i = 0; i < 4; i++) c[mt][nt][i] = 0.f;

    float4 pa[4];
    uint4 pbh[2], pbl[2];
#define LOADG(S)                                                                 \
    do {                                                                         \
        const int k0 = (S) * 32;                                                 \
        _Pragma("unroll")                                                        \
        for (int j = 0; j < 4; j++) {                                            \
            const int idx = j * 256 + t;                                         \
            const int r = idx >> 3, c4 = (idx & 7) * 4;                          \
            pa[j] = *(const float4*)(A + (row0 + r) * 256 + k0 + c4);            \
        }                                                                        \
        _Pragma("unroll")                                                        \
        for (int j = 0; j < 2; j++) {                                            \
            const int idx = j * 256 + t;                                         \
            const int r = idx >> 2, q = (idx & 3) * 8;                           \
            pbh[j] = *(const uint4*)(Wh + (size_t)(col0 + r) * 256 + k0 + q);    \
            pbl[j] = *(const uint4*)(Wl + (size_t)(col0 + r) * 256 + k0 + q);    \
        }                                                                        \
    } while (0)
#define STOREG(BUF)                                                              \
    do {                                                                         \
        _Pragma("unroll")                                                        \
        for (int j = 0; j < 4; j++) {                                            \
            const int idx = j * 256 + t;                                         \
            const int r = idx >> 3, c4 = (idx & 7) * 4;                          \
            uint32_t h01, l01, h23, l23;                                         \
            split2(pa[j].x, pa[j].y, h01, l01);                                  \
            split2(pa[j].z, pa[j].w, h23, l23);                                  \
            *(uint2*)AHp(BUF, r, c4) = make_uint2(h01, h23);                     \
            *(uint2*)ALp(BUF, r, c4) = make_uint2(l01, l23);                     \
        }                                                                        \
        _Pragma("unroll")                                                        \
        for (int j = 0; j < 2; j++) {                                            \
            const int idx = j * 256 + t;                                         \
            const int r = idx >> 2, q = (idx & 3) * 8;                           \
            *(uint4*)BHp(BUF, r, q) = pbh[j];                                    \
            *(uint4*)BLp(BUF, r, q) = pbl[j];                                    \
        }                                                                        \
    } while (0)

    LOADG(0);
    STOREG(0);
    __syncthreads();

    const int arow = (lane & 7) + ((lane >> 3) & 1) * 8;
    const int aksh = ((lane >> 4) & 1) * 8;
    const int brow = (lane & 7) + ((lane >> 4) & 1) * 8;
    const int bksh = ((lane >> 3) & 1) * 8;

    for (int s = 0; s < 8; s++) {
        const int cur = s & 1;
        if (s < 7) LOADG(s + 1);
#pragma unroll
        for (int kk = 0; kk < 2; kk++) {
            const int kb = kk * 16;
            uint32_t ah[4][4], al[4][4];
#pragma unroll
            for (int mt = 0; mt < 4; mt++) {
                const int r = wm * 64 + mt * 16 + arow;
                LDM4(ah[mt][0], ah[mt][1], ah[mt][2], ah[mt][3],
                     s2u(AHp(cur, r, kb + aksh)));
                LDM4(al[mt][0], al[mt][1], al[mt][2], al[mt][3],
                     s2u(ALp(cur, r, kb + aksh)));
            }
#pragma unroll
            for (int ntp = 0; ntp < 2; ntp++) {
                const int nr = wn * 32 + ntp * 16 + brow;
                uint32_t bh[4], bl[4];
                LDM4(bh[0], bh[1], bh[2], bh[3], s2u(BHp(cur, nr, kb + bksh)));
                LDM4(bl[0], bl[1], bl[2], bl[3], s2u(BLp(cur, nr, kb + bksh)));
#pragma unroll
                for (int mt = 0; mt < 4; mt++) {
                    mma16(c[mt][2 * ntp], ah[mt], bh);
                    mma16(c[mt][2 * ntp], ah[mt], bl);
                    mma16(c[mt][2 * ntp], al[mt], bh);
                    mma16(c[mt][2 * ntp + 1], ah[mt], bh + 2);
                    mma16(c[mt][2 * ntp + 1], ah[mt], bl + 2);
                    mma16(c[mt][2 * ntp + 1], al[mt], bh + 2);
                }
            }
        }
        if (s < 7) STOREG(cur ^ 1);
        __syncthreads();
    }

    // ---- epilogue ----
#pragma unroll
    for (int mt = 0; mt < 4; mt++) {
        const int rbase = wm * 64 + mt * 16 + gid;
#pragma unroll
        for (int h8 = 0; h8 < 2; h8++) {
            const size_t grow = row0 + rbase + h8 * 8;
#pragma unroll
            for (int nt = 0; nt < 4; nt++) {
                const int cib = wn * 32 + nt * 8 + t4 * 2;
                const float v0 = c[mt][nt][h8 * 2 + 0];
                const float v1 = c[mt][nt][h8 * 2 + 1];
                if (mode) {
                    const float2 pbv = *(const float2*)(pb + col0 + cib);
                    float2 o2; o2.x = v0 + pbv.x; o2.y = v1 + pbv.y;
                    *(float2*)(outp + grow * 256 + col0 + cib) = o2;
                } else {
                    const int region = col0 >> 8;          // 0=q 1=k 2=v
                    const int c2 = col0 - (region << 8) + cib;
                    const float* bias = (region == 0) ? bq
                                       : (region == 1) ? bkv : (bkv + 256);
                    const float2 bv = *(const float2*)(bias + c2);
                    const float scl = (region == 0) ? 0.17677669529663687f : 1.0f;
                    float* dst = (region == 0) ? g_q : (region == 1) ? g_k : g_v;
                    const int win = (int)(grow >> 6), nn = (int)(grow & 63);
                    const int hh = c2 >> 5, d = c2 & 31;
                    float2 o2;
                    o2.x = (v0 + bv.x) * scl;
                    o2.y = (v1 + bv.y) * scl;
                    *(float2*)(dst + (((size_t)win * NHEADS + hh) * NTOK + nn) * HD + d) = o2;
                }
            }
        }
    }
#undef LOADG
#undef STOREG
}

// ---------------------------------------------------------------------------
// bf16 hi/lo tensor-core attention. Block = one (b,h), 128 thr / 4 warps;
// warp w owns rows [16w, 16w+16).
// ---------------------------------------------------------------------------
__global__ __launch_bounds__(128) void attn_bf16(const float* __restrict__ w)
{
    __shared__ __nv_bfloat16 Kh[64][40], Kl[64][40];     // [m][k]
    __shared__ __nv_bfloat16 Qh[64][40], Ql[64][40];     // [m][k]
    __shared__ __nv_bfloat16 Vth[32][72], Vtl[32][72];   // [d][m]
    __shared__ __nv_bfloat16 Sh[4][16][72], Sl[4][16][72];

    const int bh = blockIdx.x, h = bh & 7;
    const int t = threadIdx.x, lane = t & 31, wid = t >> 5;
    const int gid = lane >> 2, t4 = lane & 3;

    const float* kb = g_k + (size_t)bh * 2048;
    const float* vb = g_v + (size_t)bh * 2048;
    const float* qb = g_q + (size_t)bh * 2048;

    // ---- fill: K,Q [m][k] hi/lo; V transposed [d][m] hi/lo ----
#pragma unroll
    for (int j = 0; j < 4; j++) {
        const int idx = j * 128 + t;
        const int m = idx >> 3, c4 = (idx & 7) * 4;
        const float4 kv = *(const float4*)(kb + m * 32 + c4);
        const float4 qv = *(const float4*)(qb + m * 32 + c4);
        const float4 vv = *(const float4*)(vb + m * 32 + c4);
        const float kin[4] = {kv.x, kv.y, kv.z, kv.w};
        const float qin[4] = {qv.x, qv.y, qv.z, qv.w};
        const float vin[4] = {vv.x, vv.y, vv.z, vv.w};
#pragma unroll
        for (int e = 0; e < 4; e++) {
            __nv_bfloat16 hh, ll;
            split1(kin[e], hh, ll); Kh[m][c4 + e] = hh; Kl[m][c4 + e] = ll;
            split1(qin[e], hh, ll); Qh[m][c4 + e] = hh; Ql[m][c4 + e] = ll;
            split1(vin[e], hh, ll); Vth[c4 + e][m] = hh; Vtl[c4 + e][m] = ll;
        }
    }
    __syncthreads();

    const int arow = (lane & 7) + ((lane >> 3) & 1) * 8;
    const int aksh = ((lane >> 4) & 1) * 8;
    const int brow = (lane & 7) + ((lane >> 4) & 1) * 8;
    const int bksh = ((lane >> 3) & 1) * 8;

    // ---- S = Q@K^T (3-term hi/lo), K-depth 32 ----
    float c[8][4];
#pragma unroll
    for (int nt = 0; nt < 8; nt++)
#pragma unroll
        for (int i = 0; i < 4; i++) c[nt][i] = 0.f;

#pragma unroll
    for (int kk = 0; kk < 2; kk++) {
        const int kb16 = kk * 16;
        uint32_t ah[4], al[4];
        LDM4(ah[0], ah[1], ah[2], ah[3], s2u(&Qh[wid * 16 + arow][kb16 + aksh]));
        LDM4(al[0], al[1], al[2], al[3], s2u(&Ql[wid * 16 + arow][kb16 + aksh]));
#pragma unroll
        for (int ntp = 0; ntp < 4; ntp++) {
            uint32_t bhf[4], blf[4];
            LDM4(bhf[0], bhf[1], bhf[2], bhf[3],
                 s2u(&Kh[ntp * 16 + brow][kb16 + bksh]));
            LDM4(blf[0], blf[1], blf[2], blf[3],
                 s2u(&Kl[ntp * 16 + brow][kb16 + bksh]));
            mma16(c[2 * ntp], ah, bhf);
            mma16(c[2 * ntp], ah, blf);
            mma16(c[2 * ntp], al, bhf);
            mma16(c[2 * ntp + 1], ah, bhf + 2);
            mma16(c[2 * ntp + 1], ah, blf + 2);
            mma16(c[2 * ntp + 1], al, bhf + 2);
        }
    }

    // ---- bias add ----
    const int r0 = wid * 16 + gid;
    const float* b0p = g_bias + ((size_t)h * 64 + r0) * 64;
    const float* b1p = b0p + 8 * 64;
#pragma unroll
    for (int nt = 0; nt < 8; nt++) {
        const int cc = nt * 8 + 2 * t4;
        const float2 x0 = *(const float2*)(b0p + cc);
        const float2 x1 = *(const float2*)(b1p + cc);
        c[nt][0] += x0.x; c[nt][1] += x0.y;
        c[nt][2] += x1.x; c[nt][3] += x1.y;
    }

    // ---- softmax sums (4-lane shfl) ----
    float p0 = 0.f, p1 = 0.f;
#pragma unroll
    for (int nt = 0; nt < 8; nt++) {
        p0 += __expf(c[nt][0]) + __expf(c[nt][1]);
        p1 += __expf(c[nt][2]) + __expf(c[nt][3]);
    }
    p0 += __shfl_xor_sync(0xFFFFFFFF, p0, 1);
    p0 += __shfl_xor_sync(0xFFFFFFFF, p0, 2);
    p1 += __shfl_xor_sync(0xFFFFFFFF, p1, 1);
    p1 += __shfl_xor_sync(0xFFFFFFFF, p1, 2);

    const float w0 = w[0], w1 = w[1];
    const float wm2 = fmaxf(w0, w1);
    const float e0 = __expf(w0 - wm2), e1 = __expf(w1 - wm2);
    const float winv = 1.f / (e0 + e1);
    const float ww0 = e0 * winv, ww1 = e1 * winv;
    const float k00 = ww0 / p0, k01 = ww0 / p1;

    // ---- combined weights -> smem hi/lo ----
#pragma unroll
    for (int nt = 0; nt < 8; nt++) {
        const int cc = nt * 8 + 2 * t4;
        const float r00 = fmaxf(c[nt][0], 0.f), r01 = fmaxf(c[nt][1], 0.f);
        const float r10 = fmaxf(c[nt][2], 0.f), r11 = fmaxf(c[nt][3], 0.f);
        const float a0 = __expf(c[nt][0]) * k00 + r00 * r00 * ww1;
        const float a1 = __expf(c[nt][1]) * k00 + r01 * r01 * ww1;
        const float a2 = __expf(c[nt][2]) * k01 + r10 * r10 * ww1;
        const float a3 = __expf(c[nt][3]) * k01 + r11 * r11 * ww1;
        uint32_t hi, lo;
        split2(a0, a1, hi, lo);
        *(uint32_t*)&Sh[wid][gid][cc] = hi;
        *(uint32_t*)&Sl[wid][gid][cc] = lo;
        split2(a2, a3, hi, lo);
        *(uint32_t*)&Sh[wid][gid + 8][cc] = hi;
        *(uint32_t*)&Sl[wid][gid + 8][cc] = lo;
    }
    __syncwarp();

    // ---- O = A @ V (3-term hi/lo), K-depth 64 ----
    float o[4][4];
#pragma unroll
    for (int nt = 0; nt < 4; nt++)
#pragma unroll
        for (int i = 0; i < 4; i++) o[nt][i] = 0.f;

#pragma unroll
    for (int kc = 0; kc < 4; kc++) {
        const int kb16 = kc * 16;
        uint32_t ah[4], al[4];
        LDM4(ah[0], ah[1], ah[2], ah[3], s2u(&Sh[wid][arow][kb16 + aksh]));
        LDM4(al[0], al[1], al[2], al[3], s2u(&Sl[wid][arow][kb16 + aksh]));
#pragma unroll
        for (int ntp = 0; ntp < 2; ntp++) {
            uint32_t bhf[4], blf[4];
            LDM4(bhf[0], bhf[1], bhf[2], bhf[3],
                 s2u(&Vth[ntp * 16 + brow][kb16 + bksh]));
            LDM4(blf[0], blf[1], blf[2], blf[3],
                 s2u(&Vtl[ntp * 16 + brow][kb16 + bksh]));
            mma16(o[2 * ntp], ah, bhf);
            mma16(o[2 * ntp], ah, blf);
            mma16(o[2 * ntp], al, bhf);
            mma16(o[2 * ntp + 1], ah, bhf + 2);
            mma16(o[2 * ntp + 1], ah, blf + 2);
            mma16(o[2 * ntp + 1], al, bhf + 2);
        }
    }

    // ---- write O ----
    float* ob = g_o + ((size_t)(bh >> 3) * 64) * 256 + h * 32;
#pragma unroll
    for (int nt = 0; nt < 4; nt++) {
        const int d = nt * 8 + 2 * t4;
        float2 v0; v0.x = o[nt][0]; v0.y = o[nt][1];
        float2 v1; v1.x = o[nt][2]; v1.y = o[nt][3];
        *(float2*)(ob + (size_t)r0 * 256 + d) = v0;
        *(float2*)(ob + (size_t)(r0 + 8) * 256 + d) = v1;
    }
}

// ---------------------------------------------------------------------------
extern "C" void kernel_launch(void* const* d_in, const int* in_sizes, int n_in,
                              void* d_out, int out_size)
{
    const float* x   = (const float*)d_in[0];
    const float* wq  = (const float*)d_in[1];
    const float* bq  = (const float*)d_in[2];
    const float* wkv = (const float*)d_in[3];
    const float* bkv = (const float*)d_in[4];
    const float* bt  = (const float*)d_in[5];
    const float* w   = (const float*)d_in[6];
    const float* pw  = (const float*)d_in[7];
    const float* pb  = (const float*)d_in[8];
    const int*   ri  = (const int*)d_in[9];
    float* out = (float*)d_out;

    cudaFuncSetAttribute(mm_bf16, cudaFuncAttributeMaxDynamicSharedMemorySize, MM_SMEM);

    __nv_bfloat16 *wqh, *wql, *wph, *wpl;
    float* go;
    cudaGetSymbolAddress((void**)&wqh, g_wqh);
    cudaGetSymbolAddress((void**)&wql, g_wql);
    cudaGetSymbolAddress((void**)&wph, g_wph);
    cudaGetSymbolAddress((void**)&wpl, g_wpl);
    cudaGetSymbolAddress((void**)&go,  g_o);

    prep_w<<<1024, 256>>>(wq, wkv, pw);
    prep_bias<<<128, 256>>>(bt, ri);
    mm_bf16<<<dim3(6, NROWS / 128), 256, MM_SMEM>>>(x, wqh, wql, bq, bkv, nullptr, nullptr, 0);
    attn_bf16<<<NBATCH * NHEADS, 128>>>(w);
    mm_bf16<<<dim3(2, NROWS / 128), 256, MM_SMEM>>>(go, wph, wpl, nullptr, nullptr, pb, out, 1);
}

// round 6
// speedup vs baseline: 1.1727x; 1.1727x over previous
#include <cuda_runtime.h>
#include <cuda_bf16.h>
#include <cstdint>

#define NBATCH 4096
#define NTOK   64
#define NDIM   256
#define NHEADS 8
#define HD     32
#define NROWS  (NBATCH * NTOK)   // 262144

// ---------------- device scratch (all bf16 hi/lo) ----------------------------
__device__ __align__(16) __nv_bfloat16 g_xh[(size_t)NROWS * 256];
__device__ __align__(16) __nv_bfloat16 g_xl[(size_t)NROWS * 256];
__device__ __align__(16) __nv_bfloat16 g_qh[(size_t)NBATCH * NHEADS * NTOK * HD];
__device__ __align__(16) __nv_bfloat16 g_ql[(size_t)NBATCH * NHEADS * NTOK * HD];
__device__ __align__(16) __nv_bfloat16 g_kh[(size_t)NBATCH * NHEADS * NTOK * HD];
__device__ __align__(16) __nv_bfloat16 g_kl[(size_t)NBATCH * NHEADS * NTOK * HD];
__device__ __align__(16) __nv_bfloat16 g_vh[(size_t)NBATCH * NHEADS * NTOK * HD];
__device__ __align__(16) __nv_bfloat16 g_vl[(size_t)NBATCH * NHEADS * NTOK * HD];
__device__ __align__(16) __nv_bfloat16 g_oh[(size_t)NROWS * 256];
__device__ __align__(16) __nv_bfloat16 g_ol[(size_t)NROWS * 256];
__device__ __align__(16) __nv_bfloat16 g_wqh[768 * 256];
__device__ __align__(16) __nv_bfloat16 g_wql[768 * 256];
__device__ __align__(16) __nv_bfloat16 g_wph[256 * 256];
__device__ __align__(16) __nv_bfloat16 g_wpl[256 * 256];
__device__ float g_bias[NHEADS * NTOK * NTOK];

// ---------------- helpers ----------------------------------------------------
__device__ __forceinline__ uint32_t s2u(const void* p) {
    return (uint32_t)__cvta_generic_to_shared(p);
}
__device__ __forceinline__ void split1(float a, __nv_bfloat16& h, __nv_bfloat16& l) {
    h = __float2bfloat16(a);
    l = __float2bfloat16(a - __bfloat162float(h));
}
__device__ __forceinline__ void split2(float a, float b, uint32_t& hi, uint32_t& lo) {
    __nv_bfloat16 ha, la, hb, lb;
    split1(a, ha, la); split1(b, hb, lb);
    __nv_bfloat162 H = __halves2bfloat162(ha, hb);
    __nv_bfloat162 L = __halves2bfloat162(la, lb);
    hi = *(uint32_t*)&H; lo = *(uint32_t*)&L;
}
#define LDM4(r0, r1, r2, r3, addr)                                              \
    asm volatile("ldmatrix.sync.aligned.m8n8.x4.shared.b16 {%0,%1,%2,%3}, [%4];"\
                 : "=r"(r0), "=r"(r1), "=r"(r2), "=r"(r3) : "r"(addr))
#define LDM4T(r0, r1, r2, r3, addr)                                             \
    asm volatile("ldmatrix.sync.aligned.m8n8.x4.trans.shared.b16 {%0,%1,%2,%3}, [%4];"\
                 : "=r"(r0), "=r"(r1), "=r"(r2), "=r"(r3) : "r"(addr))
#define CP16(dst, src)                                                          \
    asm volatile("cp.async.cg.shared.global [%0], [%1], 16;" :: "r"(dst), "l"(src))
#define CP_COMMIT() asm volatile("cp.async.commit_group;")
#define CP_WAIT0()  asm volatile("cp.async.wait_group 0;")
#define CP_WAIT1()  asm volatile("cp.async.wait_group 1;")

__device__ __forceinline__ void mma16(float* c, const uint32_t* a, const uint32_t* b) {
    asm volatile(
        "mma.sync.aligned.m16n8k16.row.col.f32.bf16.bf16.f32 "
        "{%0,%1,%2,%3}, {%4,%5,%6,%7}, {%8,%9}, {%0,%1,%2,%3};"
        : "+f"(c[0]), "+f"(c[1]), "+f"(c[2]), "+f"(c[3])
        : "r"(a[0]), "r"(a[1]), "r"(a[2]), "r"(a[3]), "r"(b[0]), "r"(b[1]));
}

// ---------------------------------------------------------------------------
// Prep kernels
// ---------------------------------------------------------------------------
__global__ void prep_w(const float* __restrict__ wq, const float* __restrict__ wkv,
                       const float* __restrict__ pw)
{
    int idx = blockIdx.x * 256 + threadIdx.x;
    if (idx < 768 * 256) {
        int c = idx >> 8, k = idx & 255;
        float v = (c < 256) ? wq[k * 256 + c] : wkv[k * 512 + (c - 256)];
        __nv_bfloat16 h, l; split1(v, h, l);
        g_wqh[idx] = h; g_wql[idx] = l;
    }
    int idx2 = idx - 768 * 256;
    if (idx2 >= 0 && idx2 < 256 * 256) {
        int c = idx2 >> 8, k = idx2 & 255;
        __nv_bfloat16 h, l; split1(pw[k * 256 + c], h, l);
        g_wph[idx2] = h; g_wpl[idx2] = l;
    }
}

__global__ void prep_x(const float* __restrict__ x)
{
    size_t i = (size_t)blockIdx.x * 256 + threadIdx.x;  // float4 index
    float4 v = ((const float4*)x)[i];
    uint32_t h01, l01, h23, l23;
    split2(v.x, v.y, h01, l01);
    split2(v.z, v.w, h23, l23);
    ((uint2*)g_xh)[i] = make_uint2(h01, h23);
    ((uint2*)g_xl)[i] = make_uint2(l01, l23);
}

__global__ void prep_bias(const float* __restrict__ bias_table,
                          const int* __restrict__ rel_idx)
{
    int idx = blockIdx.x * 256 + threadIdx.x;
    int h = idx >> 12, rm = idx & 4095;
    g_bias[idx] = bias_table[rel_idx[rm] * NHEADS + h];
}

// ---------------------------------------------------------------------------
// bf16 hi/lo GEMM, cp.async staging. C[128x128] = A[128x256] @ W^T.
// 256 thr / 8 warps (2m x 4n), warp tile 64x32, BK=32, double buffered.
// smem (bytes): per array per stage 10240 (128 rows x 80B):
//   AH buf*10240 | AL 20480+ | BH 40960+ | BL 61440+   -> 81920 total
// mode 0: qkv -> split & scatter to g_q/g_k/g_v hi/lo.  mode 1: proj -> out.
// ---------------------------------------------------------------------------
#define MM_SMEM 81920

__global__ __launch_bounds__(256) void mm_bf16(
    const __nv_bfloat16* __restrict__ Ah, const __nv_bfloat16* __restrict__ Al,
    const __nv_bfloat16* __restrict__ Wh, const __nv_bfloat16* __restrict__ Wl,
    const float* __restrict__ bq, const float* __restrict__ bkv,
    const float* __restrict__ pb, float* __restrict__ outp, int mode)
{
    extern __shared__ __align__(16) char sm[];
    const uint32_t sb = s2u(sm);
    const int t = threadIdx.x;
    const int lane = t & 31, wid = t >> 5;
    const int wm = wid & 1, wn = wid >> 1;
    const int gid = lane >> 2, t4 = lane & 3;
    const size_t row0 = (size_t)blockIdx.y * 128;
    const int col0 = blockIdx.x * 128;

    float c[4][4][4];
#pragma unroll
    for (int mt = 0; mt < 4; mt++)
#pragma unroll
        for (int nt = 0; nt < 4; nt++)
#pragma unroll
            for (int i = 0; i < 4; i++) c[mt][nt][i] = 0.f;

#define LOADG(S, BUF)                                                            \
    do {                                                                         \
        const int k0 = (S) * 32;                                                 \
        _Pragma("unroll")                                                        \
        for (int j = 0; j < 2; j++) {                                            \
            const int idx = j * 256 + t;                                         \
            const int r = idx >> 2, q = idx & 3;                                 \
            const uint32_t doff = (uint32_t)((BUF) * 10240 + r * 80 + q * 16);   \
            const size_t aoff = (row0 + r) * 256 + k0 + q * 8;                   \
            const size_t boff = (size_t)(col0 + r) * 256 + k0 + q * 8;           \
            CP16(sb + doff,         Ah + aoff);                                  \
            CP16(sb + 20480 + doff, Al + aoff);                                  \
            CP16(sb + 40960 + doff, Wh + boff);                                  \
            CP16(sb + 61440 + doff, Wl + boff);                                  \
        }                                                                        \
        CP_COMMIT();                                                             \
    } while (0)

    LOADG(0, 0);

    const int arow = (lane & 7) + ((lane >> 3) & 1) * 8;
    const int aksh = ((lane >> 4) & 1) * 8;
    const int brow = (lane & 7) + ((lane >> 4) & 1) * 8;
    const int bksh = ((lane >> 3) & 1) * 8;

    for (int s = 0; s < 8; s++) {
        const int cur = s & 1;
        if (s < 7) { LOADG(s + 1, cur ^ 1); CP_WAIT1(); }
        else       { CP_WAIT0(); }
        __syncthreads();
#pragma unroll
        for (int kk = 0; kk < 2; kk++) {
            const int kb = kk * 16;
            uint32_t ah[4][4], al[4][4];
#pragma unroll
            for (int mt = 0; mt < 4; mt++) {
                const int r = wm * 64 + mt * 16 + arow;
                const uint32_t aoff = (uint32_t)(cur * 10240 + r * 80 + (kb + aksh) * 2);
                LDM4(ah[mt][0], ah[mt][1], ah[mt][2], ah[mt][3], sb + aoff);
                LDM4(al[mt][0], al[mt][1], al[mt][2], al[mt][3], sb + 20480 + aoff);
            }
#pragma unroll
            for (int ntp = 0; ntp < 2; ntp++) {
                const int nr = wn * 32 + ntp * 16 + brow;
                const uint32_t boff = (uint32_t)(cur * 10240 + nr * 80 + (kb + bksh) * 2);
                uint32_t bh[4], bl[4];
                LDM4(bh[0], bh[1], bh[2], bh[3], sb + 40960 + boff);
                LDM4(bl[0], bl[1], bl[2], bl[3], sb + 61440 + boff);
#pragma unroll
                for (int mt = 0; mt < 4; mt++) {
                    mma16(c[mt][2 * ntp], ah[mt], bh);
                    mma16(c[mt][2 * ntp], ah[mt], bl);
                    mma16(c[mt][2 * ntp], al[mt], bh);
                    mma16(c[mt][2 * ntp + 1], ah[mt], bh + 2);
                    mma16(c[mt][2 * ntp + 1], ah[mt], bl + 2);
                    mma16(c[mt][2 * ntp + 1], al[mt], bh + 2);
                }
            }
        }
        __syncthreads();
    }

    // ---- epilogue ----
#pragma unroll
    for (int mt = 0; mt < 4; mt++) {
        const int rbase = wm * 64 + mt * 16 + gid;
#pragma unroll
        for (int h8 = 0; h8 < 2; h8++) {
            const size_t grow = row0 + rbase + h8 * 8;
#pragma unroll
            for (int nt = 0; nt < 4; nt++) {
                const int cib = wn * 32 + nt * 8 + t4 * 2;
                const float v0 = c[mt][nt][h8 * 2 + 0];
                const float v1 = c[mt][nt][h8 * 2 + 1];
                if (mode) {
                    const float2 pbv = *(const float2*)(pb + col0 + cib);
                    float2 o2; o2.x = v0 + pbv.x; o2.y = v1 + pbv.y;
                    *(float2*)(outp + grow * 256 + col0 + cib) = o2;
                } else {
                    const int region = col0 >> 8;          // 0=q 1=k 2=v
                    const int c2 = col0 - (region << 8) + cib;
                    const float* bias = (region == 0) ? bq
                                       : (region == 1) ? bkv : (bkv + 256);
                    const float2 bv = *(const float2*)(bias + c2);
                    const float scl = (region == 0) ? 0.17677669529663687f : 1.0f;
                    __nv_bfloat16* dh = (region == 0) ? g_qh : (region == 1) ? g_kh : g_vh;
                    __nv_bfloat16* dl = (region == 0) ? g_ql : (region == 1) ? g_kl : g_vl;
                    const int win = (int)(grow >> 6), nn = (int)(grow & 63);
                    const int hh = c2 >> 5, d = c2 & 31;
                    uint32_t hi, lo;
                    split2((v0 + bv.x) * scl, (v1 + bv.y) * scl, hi, lo);
                    const size_t di = (((size_t)win * NHEADS + hh) * NTOK + nn) * HD + d;
                    *(uint32_t*)(dh + di) = hi;
                    *(uint32_t*)(dl + di) = lo;
                }
            }
        }
    }
#undef LOADG
}

// ---------------------------------------------------------------------------
// Attention. Block = one (b,h), 128 thr / 4 warps; warp w owns rows [16w,16w+16).
// smem bytes: KH 0, KL 5120, QH 10240, QL 15360, VH 20480, VL 25600,
//             SH 30720 + wid*2304, SL 39936 + wid*2304   (total 49152)
// K/Q/V tiles are [64][40] bf16 (80B rows); S is [16][72] per warp (144B rows).
// V stays [m][d]; AV B-fragments via ldmatrix.trans.
// ---------------------------------------------------------------------------
__global__ __launch_bounds__(128) void attn_bf16(const float* __restrict__ w)
{
    extern __shared__ __align__(16) char sm[];
    const uint32_t sb = s2u(sm);
    const int bh = blockIdx.x, h = bh & 7;
    const int t = threadIdx.x, lane = t & 31, wid = t >> 5;
    const int gid = lane >> 2, t4 = lane & 3;

    // ---- async fill: q,k,v hi/lo [64][32] -> [64][40] smem ----
    {
        const size_t gbase = (size_t)bh * 2048;
#pragma unroll
        for (int j = 0; j < 2; j++) {
            const int idx = j * 128 + t;
            const int r = idx >> 2, q = idx & 3;
            const uint32_t doff = (uint32_t)(r * 80 + q * 16);
            const size_t soff = gbase + r * 32 + q * 8;
            CP16(sb + doff,         g_kh + soff);
            CP16(sb + 5120 + doff,  g_kl + soff);
            CP16(sb + 10240 + doff, g_qh + soff);
            CP16(sb + 15360 + doff, g_ql + soff);
            CP16(sb + 20480 + doff, g_vh + soff);
            CP16(sb + 25600 + doff, g_vl + soff);
        }
        CP_COMMIT();
    }
    CP_WAIT0();
    __syncthreads();

    const int arow = (lane & 7) + ((lane >> 3) & 1) * 8;
    const int aksh = ((lane >> 4) & 1) * 8;
    const int brow = (lane & 7) + ((lane >> 4) & 1) * 8;
    const int bksh = ((lane >> 3) & 1) * 8;
    // trans-ldmatrix addressing for V [m][d]
    const int vrow = (lane & 7) + ((lane >> 3) & 1) * 8;
    const int vcsh = ((lane >> 4) & 1) * 8;

    // ---- S = Q@K^T (3-term), K-depth 32 ----
    float c[8][4];
#pragma unroll
    for (int nt = 0; nt < 8; nt++)
#pragma unroll
        for (int i = 0; i < 4; i++) c[nt][i] = 0.f;

#pragma unroll
    for (int kk = 0; kk < 2; kk++) {
        const int kb16 = kk * 16;
        uint32_t ah[4], al[4];
        const uint32_t qoff = (uint32_t)((wid * 16 + arow) * 80 + (kb16 + aksh) * 2);
        LDM4(ah[0], ah[1], ah[2], ah[3], sb + 10240 + qoff);
        LDM4(al[0], al[1], al[2], al[3], sb + 15360 + qoff);
#pragma unroll
        for (int ntp = 0; ntp < 4; ntp++) {
            const uint32_t koff = (uint32_t)((ntp * 16 + brow) * 80 + (kb16 + bksh) * 2);
            uint32_t bhf[4], blf[4];
            LDM4(bhf[0], bhf[1], bhf[2], bhf[3], sb + koff);
            LDM4(blf[0], blf[1], blf[2], blf[3], sb + 5120 + koff);
            mma16(c[2 * ntp], ah, bhf);
            mma16(c[2 * ntp], ah, blf);
            mma16(c[2 * ntp], al, bhf);
            mma16(c[2 * ntp + 1], ah, bhf + 2);
            mma16(c[2 * ntp + 1], ah, blf + 2);
            mma16(c[2 * ntp + 1], al, bhf + 2);
        }
    }

    // ---- bias add ----
    const int r0 = wid * 16 + gid;
    const float* b0p = g_bias + ((size_t)h * 64 + r0) * 64;
    const float* b1p = b0p + 8 * 64;
#pragma unroll
    for (int nt = 0; nt < 8; nt++) {
        const int cc = nt * 8 + 2 * t4;
        const float2 x0 = *(const float2*)(b0p + cc);
        const float2 x1 = *(const float2*)(b1p + cc);
        c[nt][0] += x0.x; c[nt][1] += x0.y;
        c[nt][2] += x1.x; c[nt][3] += x1.y;
    }

    // ---- softmax sums ----
    float p0 = 0.f, p1 = 0.f;
#pragma unroll
    for (int nt = 0; nt < 8; nt++) {
        p0 += __expf(c[nt][0]) + __expf(c[nt][1]);
        p1 += __expf(c[nt][2]) + __expf(c[nt][3]);
    }
    p0 += __shfl_xor_sync(0xFFFFFFFF, p0, 1);
    p0 += __shfl_xor_sync(0xFFFFFFFF, p0, 2);
    p1 += __shfl_xor_sync(0xFFFFFFFF, p1, 1);
    p1 += __shfl_xor_sync(0xFFFFFFFF, p1, 2);

    const float w0 = w[0], w1 = w[1];
    const float wmx = fmaxf(w0, w1);
    const float e0 = __expf(w0 - wmx), e1 = __expf(w1 - wmx);
    const float winv = 1.f / (e0 + e1);
    const float ww0 = e0 * winv, ww1 = e1 * winv;
    const float k00 = ww0 / p0, k01 = ww0 / p1;

    // ---- combined weights -> S hi/lo smem ----
    const uint32_t sh0 = 30720 + wid * 2304;
    const uint32_t sl0 = 39936 + wid * 2304;
#pragma unroll
    for (int nt = 0; nt < 8; nt++) {
        const int cc = nt * 8 + 2 * t4;
        const float q00 = fmaxf(c[nt][0], 0.f), q01 = fmaxf(c[nt][1], 0.f);
        const float q10 = fmaxf(c[nt][2], 0.f), q11 = fmaxf(c[nt][3], 0.f);
        const float a0 = __expf(c[nt][0]) * k00 + q00 * q00 * ww1;
        const float a1 = __expf(c[nt][1]) * k00 + q01 * q01 * ww1;
        const float a2 = __expf(c[nt][2]) * k01 + q10 * q10 * ww1;
        const float a3 = __expf(c[nt][3]) * k01 + q11 * q11 * ww1;
        uint32_t hi, lo;
        split2(a0, a1, hi, lo);
        *(uint32_t*)(sm + sh0 + gid * 144 + cc * 2) = hi;
        *(uint32_t*)(sm + sl0 + gid * 144 + cc * 2) = lo;
        split2(a2, a3, hi, lo);
        *(uint32_t*)(sm + sh0 + (gid + 8) * 144 + cc * 2) = hi;
        *(uint32_t*)(sm + sl0 + (gid + 8) * 144 + cc * 2) = lo;
    }
    __syncwarp();

    // ---- O = A @ V (3-term), K-depth 64, V via ldmatrix.trans ----
    float o[4][4];
#pragma unroll
    for (int nt = 0; nt < 4; nt++)
#pragma unroll
        for (int i = 0; i < 4; i++) o[nt][i] = 0.f;

#pragma unroll
    for (int kc = 0; kc < 4; kc++) {
        const int kb16 = kc * 16;
        uint32_t ah[4], al[4];
        const uint32_t soff = (uint32_t)(arow * 144 + (kb16 + aksh) * 2);
        LDM4(ah[0], ah[1], ah[2], ah[3], sb + sh0 + soff);
        LDM4(al[0], al[1], al[2], al[3], sb + sl0 + soff);
#pragma unroll
        for (int ntp = 0; ntp < 2; ntp++) {
            const uint32_t voff =
                (uint32_t)((kb16 + vrow) * 80 + (ntp * 16 + vcsh) * 2);
            uint32_t bhf[4], blf[4];
            LDM4T(bhf[0], bhf[1], bhf[2], bhf[3], sb + 20480 + voff);
            LDM4T(blf[0], blf[1], blf[2], blf[3], sb + 25600 + voff);
            mma16(o[2 * ntp], ah, bhf);
            mma16(o[2 * ntp], ah, blf);
            mma16(o[2 * ntp], al, bhf);
            mma16(o[2 * ntp + 1], ah, bhf + 2);
            mma16(o[2 * ntp + 1], ah, blf + 2);
            mma16(o[2 * ntp + 1], al, bhf + 2);
        }
    }

    // ---- write O hi/lo ----
    const size_t obase = ((size_t)(bh >> 3) * 64) * 256 + h * 32;
#pragma unroll
    for (int nt = 0; nt < 4; nt++) {
        const int d = nt * 8 + 2 * t4;
        uint32_t hi, lo;
        split2(o[nt][0], o[nt][1], hi, lo);
        *(uint32_t*)(g_oh + obase + (size_t)r0 * 256 + d) = hi;
        *(uint32_t*)(g_ol + obase + (size_t)r0 * 256 + d) = lo;
        split2(o[nt][2], o[nt][3], hi, lo);
        *(uint32_t*)(g_oh + obase + (size_t)(r0 + 8) * 256 + d) = hi;
        *(uint32_t*)(g_ol + obase + (size_t)(r0 + 8) * 256 + d) = lo;
    }
}

// ---------------------------------------------------------------------------
extern "C" void kernel_launch(void* const* d_in, const int* in_sizes, int n_in,
                              void* d_out, int out_size)
{
    const float* x   = (const float*)d_in[0];
    const float* wq  = (const float*)d_in[1];
    const float* bq  = (const float*)d_in[2];
    const float* wkv = (const float*)d_in[3];
    const float* bkv = (const float*)d_in[4];
    const float* bt  = (const float*)d_in[5];
    const float* w   = (const float*)d_in[6];
    const float* pw  = (const float*)d_in[7];
    const float* pb  = (const float*)d_in[8];
    const int*   ri  = (const int*)d_in[9];
    float* out = (float*)d_out;

    cudaFuncSetAttribute(mm_bf16, cudaFuncAttributeMaxDynamicSharedMemorySize, MM_SMEM);

    __nv_bfloat16 *xh, *xl, *oh, *ol, *wqh, *wql, *wph, *wpl;
    cudaGetSymbolAddress((void**)&xh,  g_xh);
    cudaGetSymbolAddress((void**)&xl,  g_xl);
    cudaGetSymbolAddress((void**)&oh,  g_oh);
    cudaGetSymbolAddress((void**)&ol,  g_ol);
    cudaGetSymbolAddress((void**)&wqh, g_wqh);
    cudaGetSymbolAddress((void**)&wql, g_wql);
    cudaGetSymbolAddress((void**)&wph, g_wph);
    cudaGetSymbolAddress((void**)&wpl, g_wpl);

    prep_w<<<1024, 256>>>(wq, wkv, pw);
    prep_x<<<NROWS / 4, 256>>>(x);
    prep_bias<<<128, 256>>>(bt, ri);
    mm_bf16<<<dim3(6, NROWS / 128), 256, MM_SMEM>>>(xh, xl, wqh, wql, bq, bkv,
                                                    nullptr, nullptr, 0);
    attn_bf16<<<NBATCH * NHEADS, 128, 49152>>>(w);
    mm_bf16<<<dim3(2, NROWS / 128), 256, MM_SMEM>>>(oh, ol, wph, wpl, nullptr,
                                                    nullptr, pb, out, 1);
}

// round 7
// speedup vs baseline: 1.9211x; 1.6382x over previous
#include <cuda_runtime.h>
#include <cuda_bf16.h>
#include <cuda_fp16.h>
#include <cstdint>

#define NBATCH 4096
#define NTOK   64
#define NDIM   256
#define NHEADS 8
#define HD     32
#define NROWS  (NBATCH * NTOK)   // 262144

// ---------------- device scratch ---------------------------------------------
__device__ __align__(16) __half g_xf[(size_t)NROWS * 256];          // x fp16
__device__ __align__(16) __half g_of[(size_t)NROWS * 256];          // attn out fp16
__device__ __align__(16) __half g_wqf[768 * 256];                   // [col][k]
__device__ __align__(16) __half g_wpf[256 * 256];                   // [col][k]
__device__ __align__(16) __nv_bfloat16 g_qh[(size_t)NBATCH * NHEADS * NTOK * HD];
__device__ __align__(16) __nv_bfloat16 g_ql[(size_t)NBATCH * NHEADS * NTOK * HD];
__device__ __align__(16) __nv_bfloat16 g_kh[(size_t)NBATCH * NHEADS * NTOK * HD];
__device__ __align__(16) __nv_bfloat16 g_kl[(size_t)NBATCH * NHEADS * NTOK * HD];
__device__ __align__(16) __nv_bfloat16 g_vh[(size_t)NBATCH * NHEADS * NTOK * HD];
__device__ __align__(16) __nv_bfloat16 g_vl[(size_t)NBATCH * NHEADS * NTOK * HD];
__device__ float g_bias[NHEADS * NTOK * NTOK];

// ---------------- helpers ----------------------------------------------------
__device__ __forceinline__ uint32_t s2u(const void* p) {
    return (uint32_t)__cvta_generic_to_shared(p);
}
__device__ __forceinline__ void split1(float a, __nv_bfloat16& h, __nv_bfloat16& l) {
    h = __float2bfloat16(a);
    l = __float2bfloat16(a - __bfloat162float(h));
}
__device__ __forceinline__ void split2(float a, float b, uint32_t& hi, uint32_t& lo) {
    __nv_bfloat16 ha, la, hb, lb;
    split1(a, ha, la); split1(b, hb, lb);
    __nv_bfloat162 H = __halves2bfloat162(ha, hb);
    __nv_bfloat162 L = __halves2bfloat162(la, lb);
    hi = *(uint32_t*)&H; lo = *(uint32_t*)&L;
}
#define LDM4(r0, r1, r2, r3, addr)                                              \
    asm volatile("ldmatrix.sync.aligned.m8n8.x4.shared.b16 {%0,%1,%2,%3}, [%4];"\
                 : "=r"(r0), "=r"(r1), "=r"(r2), "=r"(r3) : "r"(addr))
#define LDM4T(r0, r1, r2, r3, addr)                                             \
    asm volatile("ldmatrix.sync.aligned.m8n8.x4.trans.shared.b16 {%0,%1,%2,%3}, [%4];"\
                 : "=r"(r0), "=r"(r1), "=r"(r2), "=r"(r3) : "r"(addr))
#define CP16(dst, src)                                                          \
    asm volatile("cp.async.cg.shared.global [%0], [%1], 16;" :: "r"(dst), "l"(src))
#define CP_COMMIT() asm volatile("cp.async.commit_group;")
#define CP_WAIT0()  asm volatile("cp.async.wait_group 0;")
#define CP_WAIT1()  asm volatile("cp.async.wait_group 1;")

__device__ __forceinline__ void mma16(float* c, const uint32_t* a, const uint32_t* b) {
    asm volatile(
        "mma.sync.aligned.m16n8k16.row.col.f32.bf16.bf16.f32 "
        "{%0,%1,%2,%3}, {%4,%5,%6,%7}, {%8,%9}, {%0,%1,%2,%3};"
        : "+f"(c[0]), "+f"(c[1]), "+f"(c[2]), "+f"(c[3])
        : "r"(a[0]), "r"(a[1]), "r"(a[2]), "r"(a[3]), "r"(b[0]), "r"(b[1]));
}
__device__ __forceinline__ void mma16h(float* c, const uint32_t* a, const uint32_t* b) {
    asm volatile(
        "mma.sync.aligned.m16n8k16.row.col.f32.f16.f16.f32 "
        "{%0,%1,%2,%3}, {%4,%5,%6,%7}, {%8,%9}, {%0,%1,%2,%3};"
        : "+f"(c[0]), "+f"(c[1]), "+f"(c[2]), "+f"(c[3])
        : "r"(a[0]), "r"(a[1]), "r"(a[2]), "r"(a[3]), "r"(b[0]), "r"(b[1]));
}

// ---------------------------------------------------------------------------
// Prep kernels
// ---------------------------------------------------------------------------
__global__ void prep_w(const float* __restrict__ wq, const float* __restrict__ wkv,
                       const float* __restrict__ pw)
{
    int idx = blockIdx.x * 256 + threadIdx.x;
    if (idx < 768 * 256) {
        int c = idx >> 8, k = idx & 255;
        float v = (c < 256) ? wq[k * 256 + c] : wkv[k * 512 + (c - 256)];
        g_wqf[idx] = __float2half_rn(v);
    }
    int idx2 = idx - 768 * 256;
    if (idx2 >= 0 && idx2 < 256 * 256) {
        int c = idx2 >> 8, k = idx2 & 255;
        g_wpf[idx2] = __float2half_rn(pw[k * 256 + c]);
    }
}

__global__ void prep_x(const float* __restrict__ x)
{
    size_t i = (size_t)blockIdx.x * 256 + threadIdx.x;  // float4 index
    float4 v = ((const float4*)x)[i];
    __half2 a = __floats2half2_rn(v.x, v.y);
    __half2 b = __floats2half2_rn(v.z, v.w);
    ((uint2*)g_xf)[i] = make_uint2(*(uint32_t*)&a, *(uint32_t*)&b);
}

__global__ void prep_bias(const float* __restrict__ bias_table,
                          const int* __restrict__ rel_idx)
{
    int idx = blockIdx.x * 256 + threadIdx.x;
    int h = idx >> 12, rm = idx & 4095;
    g_bias[idx] = bias_table[rel_idx[rm] * NHEADS + h];
}

// ---------------------------------------------------------------------------
// fp16 GEMM, cp.async staging. C[128x128] = A[128x256] @ W^T.
// 256 thr / 8 warps (2m x 4n), warp tile 64x32, BK=32, double buffered.
// smem: A stage buf*10240, B 20480 + buf*10240 (rows padded to 80B). 40KB.
// mode 0: qkv -> split bf16 hi/lo scatter to g_q/g_k/g_v. mode 1: proj -> out.
// ---------------------------------------------------------------------------
__global__ __launch_bounds__(256) void mm_fp16(
    const __half* __restrict__ A, const __half* __restrict__ W,
    const float* __restrict__ bq, const float* __restrict__ bkv,
    const float* __restrict__ pb, float* __restrict__ outp, int mode)
{
    extern __shared__ __align__(16) char sm[];
    const uint32_t sb = s2u(sm);
    const int t = threadIdx.x;
    const int lane = t & 31, wid = t >> 5;
    const int wm = wid & 1, wn = wid >> 1;
    const int gid = lane >> 2, t4 = lane & 3;
    const size_t row0 = (size_t)blockIdx.y * 128;
    const int col0 = blockIdx.x * 128;

    float c[4][4][4];
#pragma unroll
    for (int mt = 0; mt < 4; mt++)
#pragma unroll
        for (int nt = 0; nt < 4; nt++)
#pragma unroll
            for (int i = 0; i < 4; i++) c[mt][nt][i] = 0.f;

#define LOADG(S, BUF)                                                            \
    do {                                                                         \
        const int k0 = (S) * 32;                                                 \
        _Pragma("unroll")                                                        \
        for (int j = 0; j < 2; j++) {                                            \
            const int idx = j * 256 + t;                                         \
            const int r = idx >> 2, q = idx & 3;                                 \
            const uint32_t doff = (uint32_t)((BUF) * 10240 + r * 80 + q * 16);   \
            CP16(sb + doff,         A + (row0 + r) * 256 + k0 + q * 8);          \
            CP16(sb + 20480 + doff, W + (size_t)(col0 + r) * 256 + k0 + q * 8);  \
        }                                                                        \
        CP_COMMIT();                                                             \
    } while (0)

    LOADG(0, 0);

    const int arow = (lane & 7) + ((lane >> 3) & 1) * 8;
    const int aksh = ((lane >> 4) & 1) * 8;
    const int brow = (lane & 7) + ((lane >> 4) & 1) * 8;
    const int bksh = ((lane >> 3) & 1) * 8;

    for (int s = 0; s < 8; s++) {
        const int cur = s & 1;
        if (s < 7) { LOADG(s + 1, cur ^ 1); CP_WAIT1(); }
        else       { CP_WAIT0(); }
        __syncthreads();
#pragma unroll
        for (int kk = 0; kk < 2; kk++) {
            const int kb = kk * 16;
            uint32_t a[4][4];
#pragma unroll
            for (int mt = 0; mt < 4; mt++) {
                const int r = wm * 64 + mt * 16 + arow;
                const uint32_t aoff = (uint32_t)(cur * 10240 + r * 80 + (kb + aksh) * 2);
                LDM4(a[mt][0], a[mt][1], a[mt][2], a[mt][3], sb + aoff);
            }
#pragma unroll
            for (int ntp = 0; ntp < 2; ntp++) {
                const int nr = wn * 32 + ntp * 16 + brow;
                const uint32_t boff =
                    (uint32_t)(20480 + cur * 10240 + nr * 80 + (kb + bksh) * 2);
                uint32_t b[4];
                LDM4(b[0], b[1], b[2], b[3], sb + boff);
#pragma unroll
                for (int mt = 0; mt < 4; mt++) {
                    mma16h(c[mt][2 * ntp],     a[mt], b);
                    mma16h(c[mt][2 * ntp + 1], a[mt], b + 2);
                }
            }
        }
        __syncthreads();
    }

    // ---- epilogue ----
#pragma unroll
    for (int mt = 0; mt < 4; mt++) {
        const int rbase = wm * 64 + mt * 16 + gid;
#pragma unroll
        for (int h8 = 0; h8 < 2; h8++) {
            const size_t grow = row0 + rbase + h8 * 8;
#pragma unroll
            for (int nt = 0; nt < 4; nt++) {
                const int cib = wn * 32 + nt * 8 + t4 * 2;
                const float v0 = c[mt][nt][h8 * 2 + 0];
                const float v1 = c[mt][nt][h8 * 2 + 1];
                if (mode) {
                    const float2 pbv = *(const float2*)(pb + col0 + cib);
                    float2 o2; o2.x = v0 + pbv.x; o2.y = v1 + pbv.y;
                    *(float2*)(outp + grow * 256 + col0 + cib) = o2;
                } else {
                    const int region = col0 >> 8;          // 0=q 1=k 2=v
                    const int c2 = col0 - (region << 8) + cib;
                    const float* bias = (region == 0) ? bq
                                       : (region == 1) ? bkv : (bkv + 256);
                    const float2 bv = *(const float2*)(bias + c2);
                    const float scl = (region == 0) ? 0.17677669529663687f : 1.0f;
                    __nv_bfloat16* dh = (region == 0) ? g_qh : (region == 1) ? g_kh : g_vh;
                    __nv_bfloat16* dl = (region == 0) ? g_ql : (region == 1) ? g_kl : g_vl;
                    const int win = (int)(grow >> 6), nn = (int)(grow & 63);
                    const int hh = c2 >> 5, d = c2 & 31;
                    uint32_t hi, lo;
                    split2((v0 + bv.x) * scl, (v1 + bv.y) * scl, hi, lo);
                    const size_t di = (((size_t)win * NHEADS + hh) * NTOK + nn) * HD + d;
                    *(uint32_t*)(dh + di) = hi;
                    *(uint32_t*)(dl + di) = lo;
                }
            }
        }
    }
#undef LOADG
}

// ---------------------------------------------------------------------------
// Attention (bf16 3-term, as R6). Block = one (b,h), 128 thr / 4 warps.
// smem bytes: KH 0, KL 5120, QH 10240, QL 15360, VH 20480, VL 25600,
//             SH 30720 + wid*2304, SL 39936 + wid*2304   (total 49152)
// ---------------------------------------------------------------------------
__global__ __launch_bounds__(128) void attn_bf16(const float* __restrict__ w)
{
    extern __shared__ __align__(16) char sm[];
    const uint32_t sb = s2u(sm);
    const int bh = blockIdx.x, h = bh & 7;
    const int t = threadIdx.x, lane = t & 31, wid = t >> 5;
    const int gid = lane >> 2, t4 = lane & 3;

    {
        const size_t gbase = (size_t)bh * 2048;
#pragma unroll
        for (int j = 0; j < 2; j++) {
            const int idx = j * 128 + t;
            const int r = idx >> 2, q = idx & 3;
            const uint32_t doff = (uint32_t)(r * 80 + q * 16);
            const size_t soff = gbase + r * 32 + q * 8;
            CP16(sb + doff,         g_kh + soff);
            CP16(sb + 5120 + doff,  g_kl + soff);
            CP16(sb + 10240 + doff, g_qh + soff);
            CP16(sb + 15360 + doff, g_ql + soff);
            CP16(sb + 20480 + doff, g_vh + soff);
            CP16(sb + 25600 + doff, g_vl + soff);
        }
        CP_COMMIT();
    }
    CP_WAIT0();
    __syncthreads();

    const int arow = (lane & 7) + ((lane >> 3) & 1) * 8;
    const int aksh = ((lane >> 4) & 1) * 8;
    const int brow = (lane & 7) + ((lane >> 4) & 1) * 8;
    const int bksh = ((lane >> 3) & 1) * 8;
    const int vrow = (lane & 7) + ((lane >> 3) & 1) * 8;
    const int vcsh = ((lane >> 4) & 1) * 8;

    // ---- S = Q@K^T (3-term) ----
    float c[8][4];
#pragma unroll
    for (int nt = 0; nt < 8; nt++)
#pragma unroll
        for (int i = 0; i < 4; i++) c[nt][i] = 0.f;

#pragma unroll
    for (int kk = 0; kk < 2; kk++) {
        const int kb16 = kk * 16;
        uint32_t ah[4], al[4];
        const uint32_t qoff = (uint32_t)((wid * 16 + arow) * 80 + (kb16 + aksh) * 2);
        LDM4(ah[0], ah[1], ah[2], ah[3], sb + 10240 + qoff);
        LDM4(al[0], al[1], al[2], al[3], sb + 15360 + qoff);
#pragma unroll
        for (int ntp = 0; ntp < 4; ntp++) {
            const uint32_t koff = (uint32_t)((ntp * 16 + brow) * 80 + (kb16 + bksh) * 2);
            uint32_t bhf[4], blf[4];
            LDM4(bhf[0], bhf[1], bhf[2], bhf[3], sb + koff);
            LDM4(blf[0], blf[1], blf[2], blf[3], sb + 5120 + koff);
            mma16(c[2 * ntp], ah, bhf);
            mma16(c[2 * ntp], ah, blf);
            mma16(c[2 * ntp], al, bhf);
            mma16(c[2 * ntp + 1], ah, bhf + 2);
            mma16(c[2 * ntp + 1], ah, blf + 2);
            mma16(c[2 * ntp + 1], al, bhf + 2);
        }
    }

    // ---- bias add ----
    const int r0 = wid * 16 + gid;
    const float* b0p = g_bias + ((size_t)h * 64 + r0) * 64;
    const float* b1p = b0p + 8 * 64;
#pragma unroll
    for (int nt = 0; nt < 8; nt++) {
        const int cc = nt * 8 + 2 * t4;
        const float2 x0 = *(const float2*)(b0p + cc);
        const float2 x1 = *(const float2*)(b1p + cc);
        c[nt][0] += x0.x; c[nt][1] += x0.y;
        c[nt][2] += x1.x; c[nt][3] += x1.y;
    }

    // ---- softmax sums ----
    float p0 = 0.f, p1 = 0.f;
#pragma unroll
    for (int nt = 0; nt < 8; nt++) {
        p0 += __expf(c[nt][0]) + __expf(c[nt][1]);
        p1 += __expf(c[nt][2]) + __expf(c[nt][3]);
    }
    p0 += __shfl_xor_sync(0xFFFFFFFF, p0, 1);
    p0 += __shfl_xor_sync(0xFFFFFFFF, p0, 2);
    p1 += __shfl_xor_sync(0xFFFFFFFF, p1, 1);
    p1 += __shfl_xor_sync(0xFFFFFFFF, p1, 2);

    const float w0 = w[0], w1 = w[1];
    const float wmx = fmaxf(w0, w1);
    const float e0 = __expf(w0 - wmx), e1 = __expf(w1 - wmx);
    const float winv = 1.f / (e0 + e1);
    const float ww0 = e0 * winv, ww1 = e1 * winv;
    const float k00 = ww0 / p0, k01 = ww0 / p1;

    // ---- combined weights -> S hi/lo smem ----
    const uint32_t sh0 = 30720 + wid * 2304;
    const uint32_t sl0 = 39936 + wid * 2304;
#pragma unroll
    for (int nt = 0; nt < 8; nt++) {
        const int cc = nt * 8 + 2 * t4;
        const float q00 = fmaxf(c[nt][0], 0.f), q01 = fmaxf(c[nt][1], 0.f);
        const float q10 = fmaxf(c[nt][2], 0.f), q11 = fmaxf(c[nt][3], 0.f);
        const float a0 = __expf(c[nt][0]) * k00 + q00 * q00 * ww1;
        const float a1 = __expf(c[nt][1]) * k00 + q01 * q01 * ww1;
        const float a2 = __expf(c[nt][2]) * k01 + q10 * q10 * ww1;
        const float a3 = __expf(c[nt][3]) * k01 + q11 * q11 * ww1;
        uint32_t hi, lo;
        split2(a0, a1, hi, lo);
        *(uint32_t*)(sm + sh0 + gid * 144 + cc * 2) = hi;
        *(uint32_t*)(sm + sl0 + gid * 144 + cc * 2) = lo;
        split2(a2, a3, hi, lo);
        *(uint32_t*)(sm + sh0 + (gid + 8) * 144 + cc * 2) = hi;
        *(uint32_t*)(sm + sl0 + (gid + 8) * 144 + cc * 2) = lo;
    }
    __syncwarp();

    // ---- O = A @ V (3-term), V via ldmatrix.trans ----
    float o[4][4];
#pragma unroll
    for (int nt = 0; nt < 4; nt++)
#pragma unroll
        for (int i = 0; i < 4; i++) o[nt][i] = 0.f;

#pragma unroll
    for (int kc = 0; kc < 4; kc++) {
        const int kb16 = kc * 16;
        uint32_t ah[4], al[4];
        const uint32_t soff = (uint32_t)(arow * 144 + (kb16 + aksh) * 2);
        LDM4(ah[0], ah[1], ah[2], ah[3], sb + sh0 + soff);
        LDM4(al[0], al[1], al[2], al[3], sb + sl0 + soff);
#pragma unroll
        for (int ntp = 0; ntp < 2; ntp++) {
            const uint32_t voff =
                (uint32_t)((kb16 + vrow) * 80 + (ntp * 16 + vcsh) * 2);
            uint32_t bhf[4], blf[4];
            LDM4T(bhf[0], bhf[1], bhf[2], bhf[3], sb + 20480 + voff);
            LDM4T(blf[0], blf[1], blf[2], blf[3], sb + 25600 + voff);
            mma16(o[2 * ntp], ah, bhf);
            mma16(o[2 * ntp], ah, blf);
            mma16(o[2 * ntp], al, bhf);
            mma16(o[2 * ntp + 1], ah, bhf + 2);
            mma16(o[2 * ntp + 1], ah, blf + 2);
            mma16(o[2 * ntp + 1], al, bhf + 2);
        }
    }

    // ---- write O (fp16, for proj) ----
    const size_t obase = ((size_t)(bh >> 3) * 64) * 256 + h * 32;
#pragma unroll
    for (int nt = 0; nt < 4; nt++) {
        const int d = nt * 8 + 2 * t4;
        __half2 v0 = __floats2half2_rn(o[nt][0], o[nt][1]);
        __half2 v1 = __floats2half2_rn(o[nt][2], o[nt][3]);
        *(uint32_t*)(g_of + obase + (size_t)r0 * 256 + d) = *(uint32_t*)&v0;
        *(uint32_t*)(g_of + obase + (size_t)(r0 + 8) * 256 + d) = *(uint32_t*)&v1;
    }
}

// ---------------------------------------------------------------------------
extern "C" void kernel_launch(void* const* d_in, const int* in_sizes, int n_in,
                              void* d_out, int out_size)
{
    const float* x   = (const float*)d_in[0];
    const float* wq  = (const float*)d_in[1];
    const float* bq  = (const float*)d_in[2];
    const float* wkv = (const float*)d_in[3];
    const float* bkv = (const float*)d_in[4];
    const float* bt  = (const float*)d_in[5];
    const float* w   = (const float*)d_in[6];
    const float* pw  = (const float*)d_in[7];
    const float* pb  = (const float*)d_in[8];
    const int*   ri  = (const int*)d_in[9];
    float* out = (float*)d_out;

    __half *xf, *of, *wqf, *wpf;
    cudaGetSymbolAddress((void**)&xf,  g_xf);
    cudaGetSymbolAddress((void**)&of,  g_of);
    cudaGetSymbolAddress((void**)&wqf, g_wqf);
    cudaGetSymbolAddress((void**)&wpf, g_wpf);

    prep_w<<<1024, 256>>>(wq, wkv, pw);
    prep_x<<<NROWS / 4, 256>>>(x);
    prep_bias<<<128, 256>>>(bt, ri);
    mm_fp16<<<dim3(6, NROWS / 128), 256, 40960>>>(xf, wqf, bq, bkv,
                                                  nullptr, nullptr, 0);
    attn_bf16<<<NBATCH * NHEADS, 128, 49152>>>(w);
    mm_fp16<<<dim3(2, NROWS / 128), 256, 40960>>>(of, wpf, nullptr, nullptr,
                                                  pb, out, 1);
}

// round 8
// speedup vs baseline: 2.2556x; 1.1741x over previous
#include <cuda_runtime.h>
#include <cuda_fp16.h>
#include <cstdint>

#define NBATCH 4096
#define NTOK   64
#define NDIM   256
#define NHEADS 8
#define HD     32
#define NROWS  (NBATCH * NTOK)   // 262144

// ---------------- device scratch ---------------------------------------------
__device__ __align__(16) __half g_xf[(size_t)NROWS * 256];
__device__ __align__(16) __half g_of[(size_t)NROWS * 256];
__device__ __align__(16) __half g_wqf[768 * 256];
__device__ __align__(16) __half g_wpf[256 * 256];
__device__ __align__(16) __half g_qh[(size_t)NBATCH * NHEADS * NTOK * HD];
__device__ __align__(16) __half g_ql[(size_t)NBATCH * NHEADS * NTOK * HD];
__device__ __align__(16) __half g_kf[(size_t)NBATCH * NHEADS * NTOK * HD];
__device__ __align__(16) __half g_vf[(size_t)NBATCH * NHEADS * NTOK * HD];
__device__ float g_bias[NHEADS * NTOK * NTOK];

// ---------------- helpers ----------------------------------------------------
__device__ __forceinline__ uint32_t s2u(const void* p) {
    return (uint32_t)__cvta_generic_to_shared(p);
}
__device__ __forceinline__ void hsplit2(float a, float b, uint32_t& hi, uint32_t& lo) {
    __half ha = __float2half_rn(a), hb = __float2half_rn(b);
    __half la = __float2half_rn(a - __half2float(ha));
    __half lb = __float2half_rn(b - __half2float(hb));
    __half2 H = __halves2half2(ha, hb);
    __half2 L = __halves2half2(la, lb);
    hi = *(uint32_t*)&H; lo = *(uint32_t*)&L;
}
#define LDM4(r0, r1, r2, r3, addr)                                              \
    asm volatile("ldmatrix.sync.aligned.m8n8.x4.shared.b16 {%0,%1,%2,%3}, [%4];"\
                 : "=r"(r0), "=r"(r1), "=r"(r2), "=r"(r3) : "r"(addr))
#define LDM4T(r0, r1, r2, r3, addr)                                             \
    asm volatile("ldmatrix.sync.aligned.m8n8.x4.trans.shared.b16 {%0,%1,%2,%3}, [%4];"\
                 : "=r"(r0), "=r"(r1), "=r"(r2), "=r"(r3) : "r"(addr))
#define CP16(dst, src)                                                          \
    asm volatile("cp.async.cg.shared.global [%0], [%1], 16;" :: "r"(dst), "l"(src))
#define CP_COMMIT() asm volatile("cp.async.commit_group;")
#define CP_WAIT0()  asm volatile("cp.async.wait_group 0;")
#define CP_WAIT1()  asm volatile("cp.async.wait_group 1;")

__device__ __forceinline__ void mma16h(float* c, const uint32_t* a, const uint32_t* b) {
    asm volatile(
        "mma.sync.aligned.m16n8k16.row.col.f32.f16.f16.f32 "
        "{%0,%1,%2,%3}, {%4,%5,%6,%7}, {%8,%9}, {%0,%1,%2,%3};"
        : "+f"(c[0]), "+f"(c[1]), "+f"(c[2]), "+f"(c[3])
        : "r"(a[0]), "r"(a[1]), "r"(a[2]), "r"(a[3]), "r"(b[0]), "r"(b[1]));
}

// ---------------------------------------------------------------------------
// One merged prep kernel: x->fp16, weights->fp16 [col][k], bias matrix.
// Block ranges: [0,65536) x | [65536,66304) wq | [66304,66560) wp | [66560,66688) bias
// ---------------------------------------------------------------------------
__global__ void prep_all(const float* __restrict__ x,
                         const float* __restrict__ wq, const float* __restrict__ wkv,
                         const float* __restrict__ pw,
                         const float* __restrict__ bias_table,
                         const int* __restrict__ rel_idx)
{
    const int bid = blockIdx.x;
    if (bid < 65536) {
        size_t i = (size_t)bid * 256 + threadIdx.x;
        float4 v = ((const float4*)x)[i];
        __half2 a = __floats2half2_rn(v.x, v.y);
        __half2 b = __floats2half2_rn(v.z, v.w);
        ((uint2*)g_xf)[i] = make_uint2(*(uint32_t*)&a, *(uint32_t*)&b);
    } else if (bid < 66304) {
        int idx = (bid - 65536) * 256 + threadIdx.x;   // [0, 196608)
        int c = idx >> 8, k = idx & 255;
        float v = (c < 256) ? wq[k * 256 + c] : wkv[k * 512 + (c - 256)];
        g_wqf[idx] = __float2half_rn(v);
    } else if (bid < 66560) {
        int idx = (bid - 66304) * 256 + threadIdx.x;   // [0, 65536)
        int c = idx >> 8, k = idx & 255;
        g_wpf[idx] = __float2half_rn(pw[k * 256 + c]);
    } else {
        int idx = (bid - 66560) * 256 + threadIdx.x;   // [0, 32768)
        int h = idx >> 12, rm = idx & 4095;
        g_bias[idx] = bias_table[rel_idx[rm] * NHEADS + h];
    }
}

// ---------------------------------------------------------------------------
// fp16 GEMM, cp.async staging, 2-stage. C[128x128] = A[128x256] @ W^T.
// 256 thr / 8 warps (2m x 4n), warp tile 64x32, BK=32. smem 40KB.
// mode 0: qkv -> q fp16 hi/lo, k/v fp16 single. mode 1: proj -> fp32 out.
// ---------------------------------------------------------------------------
__global__ __launch_bounds__(256) void mm_fp16(
    const __half* __restrict__ A, const __half* __restrict__ W,
    const float* __restrict__ bq, const float* __restrict__ bkv,
    const float* __restrict__ pb, float* __restrict__ outp, int mode)
{
    extern __shared__ __align__(16) char sm[];
    const uint32_t sb = s2u(sm);
    const int t = threadIdx.x;
    const int lane = t & 31, wid = t >> 5;
    const int wm = wid & 1, wn = wid >> 1;
    const int gid = lane >> 2, t4 = lane & 3;
    const size_t row0 = (size_t)blockIdx.y * 128;
    const int col0 = blockIdx.x * 128;

    float c[4][4][4];
#pragma unroll
    for (int mt = 0; mt < 4; mt++)
#pragma unroll
        for (int nt = 0; nt < 4; nt++)
#pragma unroll
            for (int i = 0; i < 4; i++) c[mt][nt][i] = 0.f;

#define LOADG(S, BUF)                                                            \
    do {                                                                         \
        const int k0 = (S) * 32;                                                 \
        _Pragma("unroll")                                                        \
        for (int j = 0; j < 2; j++) {                                            \
            const int idx = j * 256 + t;                                         \
            const int r = idx >> 2, q = idx & 3;                                 \
            const uint32_t doff = (uint32_t)((BUF) * 10240 + r * 80 + q * 16);   \
            CP16(sb + doff,         A + (row0 + r) * 256 + k0 + q * 8);          \
            CP16(sb + 20480 + doff, W + (size_t)(col0 + r) * 256 + k0 + q * 8);  \
        }                                                                        \
        CP_COMMIT();                                                             \
    } while (0)

    LOADG(0, 0);

    const int arow = (lane & 7) + ((lane >> 3) & 1) * 8;
    const int aksh = ((lane >> 4) & 1) * 8;
    const int brow = (lane & 7) + ((lane >> 4) & 1) * 8;
    const int bksh = ((lane >> 3) & 1) * 8;

    for (int s = 0; s < 8; s++) {
        const int cur = s & 1;
        if (s < 7) { LOADG(s + 1, cur ^ 1); CP_WAIT1(); }
        else       { CP_WAIT0(); }
        __syncthreads();
#pragma unroll
        for (int kk = 0; kk < 2; kk++) {
            const int kb = kk * 16;
            uint32_t a[4][4];
#pragma unroll
            for (int mt = 0; mt < 4; mt++) {
                const int r = wm * 64 + mt * 16 + arow;
                const uint32_t aoff = (uint32_t)(cur * 10240 + r * 80 + (kb + aksh) * 2);
                LDM4(a[mt][0], a[mt][1], a[mt][2], a[mt][3], sb + aoff);
            }
#pragma unroll
            for (int ntp = 0; ntp < 2; ntp++) {
                const int nr = wn * 32 + ntp * 16 + brow;
                const uint32_t boff =
                    (uint32_t)(20480 + cur * 10240 + nr * 80 + (kb + bksh) * 2);
                uint32_t b[4];
                LDM4(b[0], b[1], b[2], b[3], sb + boff);
#pragma unroll
                for (int mt = 0; mt < 4; mt++) {
                    mma16h(c[mt][2 * ntp],     a[mt], b);
                    mma16h(c[mt][2 * ntp + 1], a[mt], b + 2);
                }
            }
        }
        __syncthreads();
    }

    // ---- epilogue ----
#pragma unroll
    for (int mt = 0; mt < 4; mt++) {
        const int rbase = wm * 64 + mt * 16 + gid;
#pragma unroll
        for (int h8 = 0; h8 < 2; h8++) {
            const size_t grow = row0 + rbase + h8 * 8;
#pragma unroll
            for (int nt = 0; nt < 4; nt++) {
                const int cib = wn * 32 + nt * 8 + t4 * 2;
                const float v0 = c[mt][nt][h8 * 2 + 0];
                const float v1 = c[mt][nt][h8 * 2 + 1];
                if (mode) {
                    const float2 pbv = *(const float2*)(pb + col0 + cib);
                    float2 o2; o2.x = v0 + pbv.x; o2.y = v1 + pbv.y;
                    *(float2*)(outp + grow * 256 + col0 + cib) = o2;
                } else {
                    const int region = col0 >> 8;          // 0=q 1=k 2=v
                    const int c2 = col0 - (region << 8) + cib;
                    const float* bias = (region == 0) ? bq
                                       : (region == 1) ? bkv : (bkv + 256);
                    const float2 bv = *(const float2*)(bias + c2);
                    const int win = (int)(grow >> 6), nn = (int)(grow & 63);
                    const int hh = c2 >> 5, d = c2 & 31;
                    const size_t di = (((size_t)win * NHEADS + hh) * NTOK + nn) * HD + d;
                    if (region == 0) {
                        const float scl = 0.17677669529663687f;
                        uint32_t hi, lo;
                        hsplit2((v0 + bv.x) * scl, (v1 + bv.y) * scl, hi, lo);
                        *(uint32_t*)(g_qh + di) = hi;
                        *(uint32_t*)(g_ql + di) = lo;
                    } else {
                        __half2 p = __floats2half2_rn(v0 + bv.x, v1 + bv.y);
                        __half* dst = (region == 1) ? g_kf : g_vf;
                        *(uint32_t*)(dst + di) = *(uint32_t*)&p;
                    }
                }
            }
        }
    }
#undef LOADG
}

// ---------------------------------------------------------------------------
// Attention, 2-term fp16. Block = one (b,h), 128 thr / 4 warps.
// smem bytes: QH 0, QL 5120, K 10240, V 15360  (each [64][40] fp16, 80B rows)
//             SH 20480 + wid*2304, SL 29696 + wid*2304  ([16][72] fp16, 144B rows)
// total 38912
// ---------------------------------------------------------------------------
__global__ __launch_bounds__(128) void attn_f16(const float* __restrict__ w)
{
    extern __shared__ __align__(16) char sm[];
    const uint32_t sb = s2u(sm);
    const int bh = blockIdx.x, h = bh & 7;
    const int t = threadIdx.x, lane = t & 31, wid = t >> 5;
    const int gid = lane >> 2, t4 = lane & 3;

    {
        const size_t gbase = (size_t)bh * 2048;
#pragma unroll
        for (int j = 0; j < 2; j++) {
            const int idx = j * 128 + t;
            const int r = idx >> 2, q = idx & 3;
            const uint32_t doff = (uint32_t)(r * 80 + q * 16);
            const size_t soff = gbase + r * 32 + q * 8;
            CP16(sb + doff,         g_qh + soff);
            CP16(sb + 5120 + doff,  g_ql + soff);
            CP16(sb + 10240 + doff, g_kf + soff);
            CP16(sb + 15360 + doff, g_vf + soff);
        }
        CP_COMMIT();
    }
    CP_WAIT0();
    __syncthreads();

    const int arow = (lane & 7) + ((lane >> 3) & 1) * 8;
    const int aksh = ((lane >> 4) & 1) * 8;
    const int brow = (lane & 7) + ((lane >> 4) & 1) * 8;
    const int bksh = ((lane >> 3) & 1) * 8;
    const int vrow = (lane & 7) + ((lane >> 3) & 1) * 8;
    const int vcsh = ((lane >> 4) & 1) * 8;

    // ---- S = Q@K^T (2-term: qh,ql vs k) ----
    float c[8][4];
#pragma unroll
    for (int nt = 0; nt < 8; nt++)
#pragma unroll
        for (int i = 0; i < 4; i++) c[nt][i] = 0.f;

#pragma unroll
    for (int kk = 0; kk < 2; kk++) {
        const int kb16 = kk * 16;
        uint32_t ah[4], al[4];
        const uint32_t qoff = (uint32_t)((wid * 16 + arow) * 80 + (kb16 + aksh) * 2);
        LDM4(ah[0], ah[1], ah[2], ah[3], sb + qoff);
        LDM4(al[0], al[1], al[2], al[3], sb + 5120 + qoff);
#pragma unroll
        for (int ntp = 0; ntp < 4; ntp++) {
            const uint32_t koff =
                (uint32_t)(10240 + (ntp * 16 + brow) * 80 + (kb16 + bksh) * 2);
            uint32_t bk[4];
            LDM4(bk[0], bk[1], bk[2], bk[3], sb + koff);
            mma16h(c[2 * ntp],     ah, bk);
            mma16h(c[2 * ntp],     al, bk);
            mma16h(c[2 * ntp + 1], ah, bk + 2);
            mma16h(c[2 * ntp + 1], al, bk + 2);
        }
    }

    // ---- bias add ----
    const int r0 = wid * 16 + gid;
    const float* b0p = g_bias + ((size_t)h * 64 + r0) * 64;
    const float* b1p = b0p + 8 * 64;
#pragma unroll
    for (int nt = 0; nt < 8; nt++) {
        const int cc = nt * 8 + 2 * t4;
        const float2 x0 = *(const float2*)(b0p + cc);
        const float2 x1 = *(const float2*)(b1p + cc);
        c[nt][0] += x0.x; c[nt][1] += x0.y;
        c[nt][2] += x1.x; c[nt][3] += x1.y;
    }

    // ---- softmax sums ----
    float p0 = 0.f, p1 = 0.f;
#pragma unroll
    for (int nt = 0; nt < 8; nt++) {
        p0 += __expf(c[nt][0]) + __expf(c[nt][1]);
        p1 += __expf(c[nt][2]) + __expf(c[nt][3]);
    }
    p0 += __shfl_xor_sync(0xFFFFFFFF, p0, 1);
    p0 += __shfl_xor_sync(0xFFFFFFFF, p0, 2);
    p1 += __shfl_xor_sync(0xFFFFFFFF, p1, 1);
    p1 += __shfl_xor_sync(0xFFFFFFFF, p1, 2);

    const float w0 = w[0], w1 = w[1];
    const float wmx = fmaxf(w0, w1);
    const float e0 = __expf(w0 - wmx), e1 = __expf(w1 - wmx);
    const float winv = 1.f / (e0 + e1);
    const float ww0 = e0 * winv, ww1 = e1 * winv;
    const float k00 = ww0 / p0, k01 = ww0 / p1;

    // ---- combined weights -> S hi/lo fp16 smem ----
    const uint32_t sh0 = 20480 + wid * 2304;
    const uint32_t sl0 = 29696 + wid * 2304;
#pragma unroll
    for (int nt = 0; nt < 8; nt++) {
        const int cc = nt * 8 + 2 * t4;
        const float q00 = fmaxf(c[nt][0], 0.f), q01 = fmaxf(c[nt][1], 0.f);
        const float q10 = fmaxf(c[nt][2], 0.f), q11 = fmaxf(c[nt][3], 0.f);
        const float a0 = __expf(c[nt][0]) * k00 + q00 * q00 * ww1;
        const float a1 = __expf(c[nt][1]) * k00 + q01 * q01 * ww1;
        const float a2 = __expf(c[nt][2]) * k01 + q10 * q10 * ww1;
        const float a3 = __expf(c[nt][3]) * k01 + q11 * q11 * ww1;
        uint32_t hi, lo;
        hsplit2(a0, a1, hi, lo);
        *(uint32_t*)(sm + sh0 + gid * 144 + cc * 2) = hi;
        *(uint32_t*)(sm + sl0 + gid * 144 + cc * 2) = lo;
        hsplit2(a2, a3, hi, lo);
        *(uint32_t*)(sm + sh0 + (gid + 8) * 144 + cc * 2) = hi;
        *(uint32_t*)(sm + sl0 + (gid + 8) * 144 + cc * 2) = lo;
    }
    __syncwarp();

    // ---- O = A @ V (2-term), V via ldmatrix.trans ----
    float o[4][4];
#pragma unroll
    for (int nt = 0; nt < 4; nt++)
#pragma unroll
        for (int i = 0; i < 4; i++) o[nt][i] = 0.f;

#pragma unroll
    for (int kc = 0; kc < 4; kc++) {
        const int kb16 = kc * 16;
        uint32_t ah[4], al[4];
        const uint32_t soff = (uint32_t)(arow * 144 + (kb16 + aksh) * 2);
        LDM4(ah[0], ah[1], ah[2], ah[3], sb + sh0 + soff);
        LDM4(al[0], al[1], al[2], al[3], sb + sl0 + soff);
#pragma unroll
        for (int ntp = 0; ntp < 2; ntp++) {
            const uint32_t voff =
                (uint32_t)(15360 + (kb16 + vrow) * 80 + (ntp * 16 + vcsh) * 2);
            uint32_t bv[4];
            LDM4T(bv[0], bv[1], bv[2], bv[3], sb + voff);
            mma16h(o[2 * ntp],     ah, bv);
            mma16h(o[2 * ntp],     al, bv);
            mma16h(o[2 * ntp + 1], ah, bv + 2);
            mma16h(o[2 * ntp + 1], al, bv + 2);
        }
    }

    // ---- write O fp16 ----
    const size_t obase = ((size_t)(bh >> 3) * 64) * 256 + h * 32;
#pragma unroll
    for (int nt = 0; nt < 4; nt++) {
        const int d = nt * 8 + 2 * t4;
        __half2 v0 = __floats2half2_rn(o[nt][0], o[nt][1]);
        __half2 v1 = __floats2half2_rn(o[nt][2], o[nt][3]);
        *(uint32_t*)(g_of + obase + (size_t)r0 * 256 + d) = *(uint32_t*)&v0;
        *(uint32_t*)(g_of + obase + (size_t)(r0 + 8) * 256 + d) = *(uint32_t*)&v1;
    }
}

// ---------------------------------------------------------------------------
extern "C" void kernel_launch(void* const* d_in, const int* in_sizes, int n_in,
                              void* d_out, int out_size)
{
    const float* x   = (const float*)d_in[0];
    const float* wq  = (const float*)d_in[1];
    const float* bq  = (const float*)d_in[2];
    const float* wkv = (const float*)d_in[3];
    const float* bkv = (const float*)d_in[4];
    const float* bt  = (const float*)d_in[5];
    const float* w   = (const float*)d_in[6];
    const float* pw  = (const float*)d_in[7];
    const float* pb  = (const float*)d_in[8];
    const int*   ri  = (const int*)d_in[9];
    float* out = (float*)d_out;

    __half *xf, *of, *wqf, *wpf;
    cudaGetSymbolAddress((void**)&xf,  g_xf);
    cudaGetSymbolAddress((void**)&of,  g_of);
    cudaGetSymbolAddress((void**)&wqf, g_wqf);
    cudaGetSymbolAddress((void**)&wpf, g_wpf);

    prep_all<<<66688, 256>>>(x, wq, wkv, pw, bt, ri);
    mm_fp16<<<dim3(6, NROWS / 128), 256, 40960>>>(xf, wqf, bq, bkv,
                                                  nullptr, nullptr, 0);
    attn_f16<<<NBATCH * NHEADS, 128, 38912>>>(w);
    mm_fp16<<<dim3(2, NROWS / 128), 256, 40960>>>(of, wpf, nullptr, nullptr,
                                                  pb, out, 1);
}